// round 1
// baseline (speedup 1.0000x reference)
#include <cuda_runtime.h>

// ---------------------------------------------------------------------------
// EdgeDecoder: out[e] = relu([zu[row]; zr[col]] @ W1 + b1) @ W2 + b2
// Restructured: U = zu @ W1_top + b1 ; R = zr @ W1_bot
//               out[e] = relu(U[row] + R[col]) . W2 + b2
// ---------------------------------------------------------------------------

#define HDIM 128
#define MAX_USER   100000
#define MAX_RECIPE 50000

// Scratch (allocation-free rule: __device__ globals)
__device__ float g_U[(size_t)MAX_USER * HDIM];    // 51.2 MB
__device__ float g_R[(size_t)MAX_RECIPE * HDIM];  // 25.6 MB
__device__ int   g_is64;

// ---------------------------------------------------------------------------
// Index dtype sniffer: if data is int32 pairs viewed as u64, the high 32 bits
// hold the next index (uniform in [0,50000)), so P(all 64 high words == 0)
// ~ (2e-5)^64. If truly int64 (values < 50000), all high words are 0.
// Deterministic function of the input.
// ---------------------------------------------------------------------------
__global__ void detect_idx_kernel(const unsigned long long* __restrict__ p) {
    int is64 = 1;
    #pragma unroll 1
    for (int i = 0; i < 64; ++i)
        if ((p[i] >> 32) != 0ull) is64 = 0;
    g_is64 = is64;
}

// ---------------------------------------------------------------------------
// Phase 1: C[M,128] = Z[M,128] @ Wp[128,128] (+ bias)
// 128x128 output tile per block, 256 threads, 8x8 register tile per thread.
// K = 128 in one shot. Smem: Ws 64KB + As 64KB = 128KB dynamic.
// ---------------------------------------------------------------------------
__global__ __launch_bounds__(256, 1)
void precompute_kernel(const float* __restrict__ Z,
                       const float* __restrict__ Wp,
                       const float* __restrict__ bias,   // may be null
                       int which,                        // 0 -> g_U, 1 -> g_R
                       int M)
{
    extern __shared__ float smem[];
    float* Ws = smem;                 // [128][128]
    float* As = smem + HDIM * HDIM;   // [128][128] row-major (r,k)

    float* __restrict__ C = which ? g_R : g_U;

    const int tid  = threadIdx.x;
    const int row0 = blockIdx.x * 128;

    // Load W (coalesced float4 copy; conflict-free STS)
    {
        const float4* Wg  = (const float4*)Wp;
        float4*       Ws4 = (float4*)Ws;
        #pragma unroll
        for (int idx = tid; idx < 4096; idx += 256)
            Ws4[idx] = Wg[idx];
    }
    // Load A tile (rows are 512B-contiguous; guard tail rows with zeros)
    {
        float4* As4 = (float4*)As;
        #pragma unroll
        for (int idx = tid; idx < 4096; idx += 256) {
            int r  = idx >> 5;
            int gr = row0 + r;
            float4 v = make_float4(0.f, 0.f, 0.f, 0.f);
            if (gr < M) v = ((const float4*)Z)[(size_t)gr * 32 + (idx & 31)];
            As4[idx] = v;
        }
    }
    __syncthreads();

    // Thread (tr,tc) owns rows {4tr..4tr+3, 64+4tr..} x cols {4tc.., 64+4tc..}
    // -> W LDS.128 conflict-free per quarter-warp; A LDS.128 broadcast.
    const int tr = tid >> 4, tc = tid & 15;
    const int ra = tr * 4, rb = 64 + tr * 4;
    const int ca = tc * 4, cb = 64 + tc * 4;

    float acc[8][8];
    #pragma unroll
    for (int i = 0; i < 8; ++i)
        #pragma unroll
        for (int j = 0; j < 8; ++j) acc[i][j] = 0.f;

    #pragma unroll 2
    for (int k = 0; k < HDIM; k += 4) {
        float4 a[8];
        #pragma unroll
        for (int i = 0; i < 4; ++i) {
            a[i]     = *(const float4*)&As[(ra + i) * HDIM + k];
            a[i + 4] = *(const float4*)&As[(rb + i) * HDIM + k];
        }
        #pragma unroll
        for (int kk = 0; kk < 4; ++kk) {
            float4 w0 = *(const float4*)&Ws[(k + kk) * HDIM + ca];
            float4 w1 = *(const float4*)&Ws[(k + kk) * HDIM + cb];
            float wv[8] = {w0.x, w0.y, w0.z, w0.w, w1.x, w1.y, w1.z, w1.w};
            #pragma unroll
            for (int i = 0; i < 8; ++i) {
                float av = (kk == 0) ? a[i].x : (kk == 1) ? a[i].y :
                           (kk == 2) ? a[i].z : a[i].w;
                #pragma unroll
                for (int j = 0; j < 8; ++j)
                    acc[i][j] = fmaf(av, wv[j], acc[i][j]);
            }
        }
    }

    float bA[4] = {0.f, 0.f, 0.f, 0.f}, bB[4] = {0.f, 0.f, 0.f, 0.f};
    if (bias) {
        float4 t = *(const float4*)&bias[ca];
        bA[0] = t.x; bA[1] = t.y; bA[2] = t.z; bA[3] = t.w;
        float4 u = *(const float4*)&bias[cb];
        bB[0] = u.x; bB[1] = u.y; bB[2] = u.z; bB[3] = u.w;
    }

    #pragma unroll
    for (int i = 0; i < 8; ++i) {
        int r  = (i < 4) ? (ra + i) : (rb + i - 4);
        int gr = row0 + r;
        if (gr < M) {
            float4 o0 = make_float4(acc[i][0] + bA[0], acc[i][1] + bA[1],
                                    acc[i][2] + bA[2], acc[i][3] + bA[3]);
            float4 o1 = make_float4(acc[i][4] + bB[0], acc[i][5] + bB[1],
                                    acc[i][6] + bB[2], acc[i][7] + bB[3]);
            *(float4*)&C[(size_t)gr * HDIM + ca] = o0;
            *(float4*)&C[(size_t)gr * HDIM + cb] = o1;
        }
    }
}

// ---------------------------------------------------------------------------
// Phase 2: one warp per edge. Lane l handles cols [4l, 4l+4).
// Two 512B coalesced gathers per edge (U row + R row), relu+dot, shfl reduce.
// ---------------------------------------------------------------------------
__global__ __launch_bounds__(256)
void edge_kernel(const void* __restrict__ eidx,
                 const float* __restrict__ W2,
                 const float* __restrict__ b2,
                 float* __restrict__ out,
                 int E)
{
    __shared__ float w2s[HDIM];
    const int tid = threadIdx.x;
    if (tid < HDIM) w2s[tid] = W2[tid];
    __syncthreads();

    const int gw   = (blockIdx.x * 256 + tid) >> 5;   // edge id
    const int lane = tid & 31;
    if (gw >= E) return;

    int row, col;
    if (g_is64) {
        const long long* p = (const long long*)eidx;
        row = (int)p[gw];
        col = (int)p[(size_t)E + gw];
    } else {
        const int* p = (const int*)eidx;
        row = p[gw];
        col = p[(size_t)E + gw];
    }

    const float4 u = *(const float4*)&g_U[(size_t)row * HDIM + lane * 4];
    const float4 r = *(const float4*)&g_R[(size_t)col * HDIM + lane * 4];
    const float4 w = *(const float4*)&w2s[lane * 4];

    float s;
    s  = fmaxf(u.x + r.x, 0.f) * w.x;
    s += fmaxf(u.y + r.y, 0.f) * w.y;
    s += fmaxf(u.z + r.z, 0.f) * w.z;
    s += fmaxf(u.w + r.w, 0.f) * w.w;

    #pragma unroll
    for (int off = 16; off; off >>= 1)
        s += __shfl_xor_sync(0xffffffffu, s, off);

    if (lane == 0) out[gw] = s + __ldg(b2);
}

// ---------------------------------------------------------------------------
// kernel_launch: detect idx dtype -> 2 precompute GEMMs -> edge kernel.
// All plain kernel launches on the capture stream; no allocs, no syncs.
// ---------------------------------------------------------------------------
extern "C" void kernel_launch(void* const* d_in, const int* in_sizes, int n_in,
                              void* d_out, int out_size)
{
    const float* z_user   = (const float*)d_in[0];
    const float* z_recipe = (const float*)d_in[1];
    const void*  eidx     = d_in[2];
    const float* W1       = (const float*)d_in[3];
    const float* b1       = (const float*)d_in[4];
    const float* W2       = (const float*)d_in[5];
    const float* b2       = (const float*)d_in[6];
    float* out = (float*)d_out;

    const int Mu = in_sizes[0] / HDIM;
    const int Mr = in_sizes[1] / HDIM;
    const int E  = in_sizes[2] / 2;

    const int SMEM = 2 * HDIM * HDIM * (int)sizeof(float);   // 128 KB
    cudaFuncSetAttribute(precompute_kernel,
                         cudaFuncAttributeMaxDynamicSharedMemorySize, SMEM);

    detect_idx_kernel<<<1, 1>>>((const unsigned long long*)eidx);

    const int gu = (Mu + 127) / 128;
    const int gr = (Mr + 127) / 128;
    precompute_kernel<<<gu, 256, SMEM>>>(z_user,   W1,               b1,      0, Mu);
    precompute_kernel<<<gr, 256, SMEM>>>(z_recipe, W1 + HDIM * HDIM, nullptr, 1, Mr);

    edge_kernel<<<(E + 7) / 8, 256>>>(eidx, W2, b2, out, E);
}

// round 2
// speedup vs baseline: 1.2745x; 1.2745x over previous
#include <cuda_runtime.h>

// ---------------------------------------------------------------------------
// EdgeDecoder: out[e] = relu([zu[row]; zr[col]] @ W1 + b1) @ W2 + b2
// Restructured: U = zu @ W1_top + b1 ; R = zr @ W1_bot
//               out[e] = relu(U[row] + R[col]) . W2 + b2
// Precompute GEMM uses packed fma.rn.f32x2 (FFMA2) -> 2x fp32 FMA throughput.
// ---------------------------------------------------------------------------

#define HDIM 128
#define MAX_USER   100000
#define MAX_RECIPE 50000

__device__ float g_U[(size_t)MAX_USER * HDIM];    // 51.2 MB
__device__ float g_R[(size_t)MAX_RECIPE * HDIM];  // 25.6 MB
__device__ int   g_is64;

typedef unsigned long long u64;

__device__ __forceinline__ u64 pack_dup(float x) {
    u64 r;
    asm("mov.b64 %0, {%1, %1};" : "=l"(r) : "f"(x));
    return r;
}
__device__ __forceinline__ void ffma2(u64& acc, u64 a, u64 b) {
    asm("fma.rn.f32x2 %0, %1, %2, %0;" : "+l"(acc) : "l"(a), "l"(b));
}
__device__ __forceinline__ float2 unpack2(u64 v) {
    float2 f;
    asm("mov.b64 {%0, %1}, %2;" : "=f"(f.x), "=f"(f.y) : "l"(v));
    return f;
}

// ---------------------------------------------------------------------------
// Index dtype sniffer (int64 vs int32 viewed as int64 pairs).
// Values < 50000, so true-int64 data has all high words zero.
// ---------------------------------------------------------------------------
__global__ void detect_idx_kernel(const unsigned long long* __restrict__ p) {
    int is64 = 1;
    #pragma unroll
    for (int i = 0; i < 32; ++i)
        if ((p[i] >> 32) != 0ull) is64 = 0;
    g_is64 = is64;
}

// ---------------------------------------------------------------------------
// Phase 1 (merged): blocks [0, gu) compute U tiles, [gu, gu+gr) compute R.
// 128x128 tile / block, 256 threads, 8x8 per thread via FFMA2 (4 col-pairs).
// ---------------------------------------------------------------------------
__global__ __launch_bounds__(256, 1)
void precompute_kernel(const float* __restrict__ Zu,
                       const float* __restrict__ Zr,
                       const float* __restrict__ W1,
                       const float* __restrict__ b1,
                       int gu, int Mu, int Mr)
{
    extern __shared__ float smem[];
    float* Ws = smem;                 // [128][128]
    float* As = smem + HDIM * HDIM;   // [128][128]

    const bool isR = (blockIdx.x >= (unsigned)gu);
    const int  blk = isR ? (blockIdx.x - gu) : blockIdx.x;
    const int  M   = isR ? Mr : Mu;
    const float* __restrict__ Z  = isR ? Zr : Zu;
    const float* __restrict__ Wp = isR ? (W1 + HDIM * HDIM) : W1;
    float* __restrict__ C        = isR ? g_R : g_U;

    const int tid  = threadIdx.x;
    const int row0 = blk * 128;

    // Load W tile (coalesced float4)
    {
        const float4* Wg  = (const float4*)Wp;
        float4*       Ws4 = (float4*)Ws;
        #pragma unroll
        for (int idx = tid; idx < 4096; idx += 256)
            Ws4[idx] = Wg[idx];
    }
    // Load A tile (zero-pad tail rows)
    {
        float4* As4 = (float4*)As;
        #pragma unroll
        for (int idx = tid; idx < 4096; idx += 256) {
            int r  = idx >> 5;
            int gr = row0 + r;
            float4 v = make_float4(0.f, 0.f, 0.f, 0.f);
            if (gr < M) v = ((const float4*)Z)[(size_t)gr * 32 + (idx & 31)];
            As4[idx] = v;
        }
    }
    __syncthreads();

    const int tr = tid >> 4, tc = tid & 15;
    const int ra = tr * 4, rb = 64 + tr * 4;
    const int ca = tc * 4, cb = 64 + tc * 4;

    // acc2[i][p]: row i, col-pairs (ca,ca+1),(ca+2,ca+3),(cb,cb+1),(cb+2,cb+3)
    u64 acc2[8][4];
    #pragma unroll
    for (int i = 0; i < 8; ++i)
        #pragma unroll
        for (int j = 0; j < 4; ++j) acc2[i][j] = 0ull;

    #pragma unroll 2
    for (int k = 0; k < HDIM; k += 4) {
        float4 a[8];
        #pragma unroll
        for (int i = 0; i < 4; ++i) {
            a[i]     = *(const float4*)&As[(ra + i) * HDIM + k];
            a[i + 4] = *(const float4*)&As[(rb + i) * HDIM + k];
        }
        #pragma unroll
        for (int kk = 0; kk < 4; ++kk) {
            // float4-aligned smem rows -> ulonglong2 = two packed f32x2 pairs
            ulonglong2 w0 = *(const ulonglong2*)&Ws[(k + kk) * HDIM + ca];
            ulonglong2 w1 = *(const ulonglong2*)&Ws[(k + kk) * HDIM + cb];
            u64 wp[4] = {w0.x, w0.y, w1.x, w1.y};
            #pragma unroll
            for (int i = 0; i < 8; ++i) {
                float av = (kk == 0) ? a[i].x : (kk == 1) ? a[i].y :
                           (kk == 2) ? a[i].z : a[i].w;
                u64 ad = pack_dup(av);
                #pragma unroll
                for (int j = 0; j < 4; ++j)
                    ffma2(acc2[i][j], ad, wp[j]);
            }
        }
    }

    float bA[4] = {0.f, 0.f, 0.f, 0.f}, bB[4] = {0.f, 0.f, 0.f, 0.f};
    if (!isR) {
        float4 t = *(const float4*)&b1[ca];
        bA[0] = t.x; bA[1] = t.y; bA[2] = t.z; bA[3] = t.w;
        float4 u = *(const float4*)&b1[cb];
        bB[0] = u.x; bB[1] = u.y; bB[2] = u.z; bB[3] = u.w;
    }

    #pragma unroll
    for (int i = 0; i < 8; ++i) {
        int r  = (i < 4) ? (ra + i) : (rb + i - 4);
        int gr = row0 + r;
        if (gr < M) {
            float2 p0 = unpack2(acc2[i][0]), p1 = unpack2(acc2[i][1]);
            float2 p2 = unpack2(acc2[i][2]), p3 = unpack2(acc2[i][3]);
            float4 o0 = make_float4(p0.x + bA[0], p0.y + bA[1],
                                    p1.x + bA[2], p1.y + bA[3]);
            float4 o1 = make_float4(p2.x + bB[0], p2.y + bB[1],
                                    p3.x + bB[2], p3.y + bB[3]);
            *(float4*)&C[(size_t)gr * HDIM + ca] = o0;
            *(float4*)&C[(size_t)gr * HDIM + cb] = o1;
        }
    }
}

// ---------------------------------------------------------------------------
// Phase 2: two edges per warp (16 lanes each). Per lane: 2 float4 of U row,
// 2 float4 of R row -> 4 independent LDG.128 chains. 4-step shfl reduce.
// ---------------------------------------------------------------------------
__global__ __launch_bounds__(256)
void edge_kernel(const void* __restrict__ eidx,
                 const float* __restrict__ W2,
                 const float* __restrict__ b2,
                 float* __restrict__ out,
                 int E)
{
    __shared__ float w2s[HDIM];
    const int tid = threadIdx.x;
    if (tid < HDIM) w2s[tid] = W2[tid];
    __syncthreads();

    const int warp = (blockIdx.x * 256 + tid) >> 5;
    const int lane = tid & 31;
    const int half = lane >> 4;
    const int l16  = lane & 15;
    const int e    = warp * 2 + half;
    if (e >= E) return;   // whole 16-lane half exits together

    int row, col;
    if (g_is64) {
        const long long* p = (const long long*)eidx;
        row = (int)p[e];
        col = (int)p[(size_t)E + e];
    } else {
        const int* p = (const int*)eidx;
        row = p[e];
        col = p[(size_t)E + e];
    }

    const float4* Up = (const float4*)&g_U[(size_t)row * HDIM];
    const float4* Rp = (const float4*)&g_R[(size_t)col * HDIM];
    const float4  u0 = Up[l16 * 2],     u1 = Up[l16 * 2 + 1];
    const float4  r0 = Rp[l16 * 2],     r1 = Rp[l16 * 2 + 1];
    const float4  wa = ((const float4*)w2s)[l16 * 2];
    const float4  wb = ((const float4*)w2s)[l16 * 2 + 1];

    float s;
    s  = fmaxf(u0.x + r0.x, 0.f) * wa.x;
    s += fmaxf(u0.y + r0.y, 0.f) * wa.y;
    s += fmaxf(u0.z + r0.z, 0.f) * wa.z;
    s += fmaxf(u0.w + r0.w, 0.f) * wa.w;
    s += fmaxf(u1.x + r1.x, 0.f) * wb.x;
    s += fmaxf(u1.y + r1.y, 0.f) * wb.y;
    s += fmaxf(u1.z + r1.z, 0.f) * wb.z;
    s += fmaxf(u1.w + r1.w, 0.f) * wb.w;

    const unsigned mask = 0xFFFFu << (half * 16);
    #pragma unroll
    for (int off = 8; off; off >>= 1)
        s += __shfl_xor_sync(mask, s, off);

    if (l16 == 0) out[e] = s + __ldg(b2);
}

// ---------------------------------------------------------------------------
extern "C" void kernel_launch(void* const* d_in, const int* in_sizes, int n_in,
                              void* d_out, int out_size)
{
    const float* z_user   = (const float*)d_in[0];
    const float* z_recipe = (const float*)d_in[1];
    const void*  eidx     = d_in[2];
    const float* W1       = (const float*)d_in[3];
    const float* b1       = (const float*)d_in[4];
    const float* W2       = (const float*)d_in[5];
    const float* b2       = (const float*)d_in[6];
    float* out = (float*)d_out;

    const int Mu = in_sizes[0] / HDIM;
    const int Mr = in_sizes[1] / HDIM;
    const int E  = in_sizes[2] / 2;

    const int SMEM = 2 * HDIM * HDIM * (int)sizeof(float);   // 128 KB
    cudaFuncSetAttribute(precompute_kernel,
                         cudaFuncAttributeMaxDynamicSharedMemorySize, SMEM);

    detect_idx_kernel<<<1, 1>>>((const unsigned long long*)eidx);

    const int gu = (Mu + 127) / 128;
    const int gr = (Mr + 127) / 128;
    precompute_kernel<<<gu + gr, 256, SMEM>>>(z_user, z_recipe, W1, b1,
                                              gu, Mu, Mr);

    edge_kernel<<<(E + 15) / 16, 256>>>(eidx, W2, b2, out, E);
}

// round 3
// speedup vs baseline: 1.4000x; 1.0985x over previous
#include <cuda_runtime.h>
#include <cuda_fp16.h>

// ---------------------------------------------------------------------------
// EdgeDecoder: out[e] = relu([zu[row]; zr[col]] @ W1 + b1) @ W2 + b2
// Restructured: U = zu @ W1_top + b1 ; R = zr @ W1_bot  (fp32 FFMA2 GEMM)
//               stored as fp16 -> edge gather traffic halved
//               out[e] = relu(U[row] + R[col]) . W2 + b2 (fp32 dot)
// ---------------------------------------------------------------------------

#define HDIM 128
#define MAX_USER   100000
#define MAX_RECIPE 50000

__device__ __half g_U[(size_t)MAX_USER * HDIM];    // 25.6 MB
__device__ __half g_R[(size_t)MAX_RECIPE * HDIM];  // 12.8 MB
__device__ int    g_is64;

typedef unsigned long long u64;

__device__ __forceinline__ u64 pack_dup(float x) {
    u64 r;
    asm("mov.b64 %0, {%1, %1};" : "=l"(r) : "f"(x));
    return r;
}
__device__ __forceinline__ void ffma2(u64& acc, u64 a, u64 b) {
    asm("fma.rn.f32x2 %0, %1, %2, %0;" : "+l"(acc) : "l"(a), "l"(b));
}
__device__ __forceinline__ float2 unpack2(u64 v) {
    float2 f;
    asm("mov.b64 {%0, %1}, %2;" : "=f"(f.x), "=f"(f.y) : "l"(v));
    return f;
}

// ---------------------------------------------------------------------------
// Phase 1 (merged): blocks [0, gu) compute U tiles, [gu, gu+gr) compute R.
// 128x128 tile / block, 256 threads, 8x8 per thread via FFMA2.
// Block 0 thread 0 also sniffs the edge-index dtype (int64 vs int32-as-pairs:
// indices < 50000, so genuine int64 data has zero high words; int32 data has
// the next random index in the high word -> P(32 zeros) ~ 1e-150).
// ---------------------------------------------------------------------------
__global__ __launch_bounds__(256, 1)
void precompute_kernel(const float* __restrict__ Zu,
                       const float* __restrict__ Zr,
                       const float* __restrict__ W1,
                       const float* __restrict__ b1,
                       const unsigned long long* __restrict__ eidx,
                       int gu, int Mu, int Mr)
{
    extern __shared__ float smem[];
    float* Ws = smem;                 // [128][128]
    float* As = smem + HDIM * HDIM;   // [128][128]

    if (blockIdx.x == 0 && threadIdx.x == 0) {
        int is64 = 1;
        #pragma unroll
        for (int i = 0; i < 32; ++i)
            if ((eidx[i] >> 32) != 0ull) is64 = 0;
        g_is64 = is64;
    }

    const bool isR = (blockIdx.x >= (unsigned)gu);
    const int  blk = isR ? (blockIdx.x - gu) : blockIdx.x;
    const int  M   = isR ? Mr : Mu;
    const float* __restrict__ Z  = isR ? Zr : Zu;
    const float* __restrict__ Wp = isR ? (W1 + HDIM * HDIM) : W1;
    __half* __restrict__ C       = isR ? g_R : g_U;

    const int tid  = threadIdx.x;
    const int row0 = blk * 128;

    {
        const float4* Wg  = (const float4*)Wp;
        float4*       Ws4 = (float4*)Ws;
        #pragma unroll
        for (int idx = tid; idx < 4096; idx += 256)
            Ws4[idx] = Wg[idx];
    }
    {
        float4* As4 = (float4*)As;
        #pragma unroll
        for (int idx = tid; idx < 4096; idx += 256) {
            int r  = idx >> 5;
            int gr = row0 + r;
            float4 v = make_float4(0.f, 0.f, 0.f, 0.f);
            if (gr < M) v = ((const float4*)Z)[(size_t)gr * 32 + (idx & 31)];
            As4[idx] = v;
        }
    }
    __syncthreads();

    const int tr = tid >> 4, tc = tid & 15;
    const int ra = tr * 4, rb = 64 + tr * 4;
    const int ca = tc * 4, cb = 64 + tc * 4;

    u64 acc2[8][4];
    #pragma unroll
    for (int i = 0; i < 8; ++i)
        #pragma unroll
        for (int j = 0; j < 4; ++j) acc2[i][j] = 0ull;

    #pragma unroll 2
    for (int k = 0; k < HDIM; k += 4) {
        float4 a[8];
        #pragma unroll
        for (int i = 0; i < 4; ++i) {
            a[i]     = *(const float4*)&As[(ra + i) * HDIM + k];
            a[i + 4] = *(const float4*)&As[(rb + i) * HDIM + k];
        }
        #pragma unroll
        for (int kk = 0; kk < 4; ++kk) {
            ulonglong2 w0 = *(const ulonglong2*)&Ws[(k + kk) * HDIM + ca];
            ulonglong2 w1 = *(const ulonglong2*)&Ws[(k + kk) * HDIM + cb];
            u64 wp[4] = {w0.x, w0.y, w1.x, w1.y};
            #pragma unroll
            for (int i = 0; i < 8; ++i) {
                float av = (kk == 0) ? a[i].x : (kk == 1) ? a[i].y :
                           (kk == 2) ? a[i].z : a[i].w;
                u64 ad = pack_dup(av);
                #pragma unroll
                for (int j = 0; j < 4; ++j)
                    ffma2(acc2[i][j], ad, wp[j]);
            }
        }
    }

    float bA[4] = {0.f, 0.f, 0.f, 0.f}, bB[4] = {0.f, 0.f, 0.f, 0.f};
    if (!isR) {
        float4 t = *(const float4*)&b1[ca];
        bA[0] = t.x; bA[1] = t.y; bA[2] = t.z; bA[3] = t.w;
        float4 u = *(const float4*)&b1[cb];
        bB[0] = u.x; bB[1] = u.y; bB[2] = u.z; bB[3] = u.w;
    }

    #pragma unroll
    for (int i = 0; i < 8; ++i) {
        int r  = (i < 4) ? (ra + i) : (rb + i - 4);
        int gr = row0 + r;
        if (gr < M) {
            float2 p0 = unpack2(acc2[i][0]), p1 = unpack2(acc2[i][1]);
            float2 p2 = unpack2(acc2[i][2]), p3 = unpack2(acc2[i][3]);
            __half2 h0 = __float22half2_rn(make_float2(p0.x + bA[0], p0.y + bA[1]));
            __half2 h1 = __float22half2_rn(make_float2(p1.x + bA[2], p1.y + bA[3]));
            __half2 h2 = __float22half2_rn(make_float2(p2.x + bB[0], p2.y + bB[1]));
            __half2 h3 = __float22half2_rn(make_float2(p3.x + bB[2], p3.y + bB[3]));
            uint2 oa, ob;
            oa.x = *(unsigned*)&h0;  oa.y = *(unsigned*)&h1;
            ob.x = *(unsigned*)&h2;  ob.y = *(unsigned*)&h3;
            *(uint2*)&C[(size_t)gr * HDIM + ca] = oa;
            *(uint2*)&C[(size_t)gr * HDIM + cb] = ob;
        }
    }
}

// ---------------------------------------------------------------------------
// Phase 2: four edges per warp (8 lanes each). fp16 rows: 256B per row, one
// uint4 (8 halves) per lane per matrix chunk x2 chunks. fp32 dot, 3-step shfl.
// ---------------------------------------------------------------------------
__device__ __forceinline__ float dot8h(uint4 u, uint4 r, float4 w0, float4 w1) {
    const __half2 z2 = __float2half2_rn(0.f);
    __half2 a0 = __hmax2(__hadd2(*(__half2*)&u.x, *(__half2*)&r.x), z2);
    __half2 a1 = __hmax2(__hadd2(*(__half2*)&u.y, *(__half2*)&r.y), z2);
    __half2 a2 = __hmax2(__hadd2(*(__half2*)&u.z, *(__half2*)&r.z), z2);
    __half2 a3 = __hmax2(__hadd2(*(__half2*)&u.w, *(__half2*)&r.w), z2);
    float2 f0 = __half22float2(a0);
    float2 f1 = __half22float2(a1);
    float2 f2 = __half22float2(a2);
    float2 f3 = __half22float2(a3);
    float s;
    s  = f0.x * w0.x;
    s  = fmaf(f0.y, w0.y, s);
    s  = fmaf(f1.x, w0.z, s);
    s  = fmaf(f1.y, w0.w, s);
    s  = fmaf(f2.x, w1.x, s);
    s  = fmaf(f2.y, w1.y, s);
    s  = fmaf(f3.x, w1.z, s);
    s  = fmaf(f3.y, w1.w, s);
    return s;
}

__global__ __launch_bounds__(256)
void edge_kernel(const void* __restrict__ eidx,
                 const float* __restrict__ W2,
                 const float* __restrict__ b2,
                 float* __restrict__ out,
                 int E)
{
    __shared__ float w2s[HDIM];
    const int tid = threadIdx.x;
    if (tid < HDIM) w2s[tid] = W2[tid];
    __syncthreads();

    const int warp = (blockIdx.x * 256 + tid) >> 5;
    const int lane = tid & 31;
    const int sub  = lane >> 3;       // edge slot within warp (0..3)
    const int l8   = lane & 7;        // lane within edge group
    const int e    = warp * 4 + sub;
    if (e >= E) return;               // whole 8-lane group exits together

    int row, col;
    if (g_is64) {
        const long long* p = (const long long*)eidx;
        row = (int)p[e];
        col = (int)p[(size_t)E + e];
    } else {
        const int* p = (const int*)eidx;
        row = p[e];
        col = p[(size_t)E + e];
    }

    // fp16 rows: 128 halves = 256B = 16 uint4. Lane handles cols [l8*16, +16).
    const uint4* Up = (const uint4*)&g_U[(size_t)row * HDIM];
    const uint4* Rp = (const uint4*)&g_R[(size_t)col * HDIM];
    const uint4 ua = Up[l8 * 2],     ub = Up[l8 * 2 + 1];
    const uint4 ra = Rp[l8 * 2],     rb = Rp[l8 * 2 + 1];

    const float4* w4 = (const float4*)w2s;
    const float4 w0 = w4[l8 * 4],     w1 = w4[l8 * 4 + 1];
    const float4 w2 = w4[l8 * 4 + 2], w3 = w4[l8 * 4 + 3];

    float s = dot8h(ua, ra, w0, w1) + dot8h(ub, rb, w2, w3);

    const unsigned mask = 0xFFu << (sub * 8);
    #pragma unroll
    for (int off = 4; off; off >>= 1)
        s += __shfl_xor_sync(mask, s, off);

    if (l8 == 0) out[e] = s + __ldg(b2);
}

// ---------------------------------------------------------------------------
extern "C" void kernel_launch(void* const* d_in, const int* in_sizes, int n_in,
                              void* d_out, int out_size)
{
    const float* z_user   = (const float*)d_in[0];
    const float* z_recipe = (const float*)d_in[1];
    const void*  eidx     = d_in[2];
    const float* W1       = (const float*)d_in[3];
    const float* b1       = (const float*)d_in[4];
    const float* W2       = (const float*)d_in[5];
    const float* b2       = (const float*)d_in[6];
    float* out = (float*)d_out;

    const int Mu = in_sizes[0] / HDIM;
    const int Mr = in_sizes[1] / HDIM;
    const int E  = in_sizes[2] / 2;

    const int SMEM = 2 * HDIM * HDIM * (int)sizeof(float);   // 128 KB
    cudaFuncSetAttribute(precompute_kernel,
                         cudaFuncAttributeMaxDynamicSharedMemorySize, SMEM);

    const int gu = (Mu + 127) / 128;
    const int gr = (Mr + 127) / 128;
    precompute_kernel<<<gu + gr, 256, SMEM>>>(z_user, z_recipe, W1, b1,
                                              (const unsigned long long*)eidx,
                                              gu, Mu, Mr);

    edge_kernel<<<(E + 31) / 32, 256>>>(eidx, W2, b2, out, E);
}

// round 4
// speedup vs baseline: 1.6217x; 1.1583x over previous
#include <cuda_runtime.h>
#include <cuda_fp16.h>

// ---------------------------------------------------------------------------
// EdgeDecoder: out[e] = relu([zu[row]; zr[col]] @ W1 + b1) @ W2 + b2
// Restructured: U = zu @ W1_top + b1 ; R = zr @ W1_bot  (fp32 FFMA2 GEMM)
//               stored as fp16 -> edge gather traffic halved
//               out[e] = relu(U[row] + R[col]) . W2 + b2 (fp32 dot)
// R4: edge gather re-laid out so each LDG.128 group covers one full 128B
//     line (lane l8 -> chunks l8 and l8+8), halving L1tex wavefronts.
// ---------------------------------------------------------------------------

#define HDIM 128
#define MAX_USER   100000
#define MAX_RECIPE 50000

__device__ __half g_U[(size_t)MAX_USER * HDIM];    // 25.6 MB
__device__ __half g_R[(size_t)MAX_RECIPE * HDIM];  // 12.8 MB
__device__ int    g_is64;

typedef unsigned long long u64;

__device__ __forceinline__ u64 pack_dup(float x) {
    u64 r;
    asm("mov.b64 %0, {%1, %1};" : "=l"(r) : "f"(x));
    return r;
}
__device__ __forceinline__ void ffma2(u64& acc, u64 a, u64 b) {
    asm("fma.rn.f32x2 %0, %1, %2, %0;" : "+l"(acc) : "l"(a), "l"(b));
}
__device__ __forceinline__ float2 unpack2(u64 v) {
    float2 f;
    asm("mov.b64 {%0, %1}, %2;" : "=f"(f.x), "=f"(f.y) : "l"(v));
    return f;
}

// ---------------------------------------------------------------------------
// Phase 1 (merged): blocks [0, gu) compute U tiles, [gu, gu+gr) compute R.
// 128x128 tile / block, 256 threads, 8x8 per thread via FFMA2.
// Block 0 thread 0 sniffs edge-index dtype (int64 vs int32-as-pairs).
// ---------------------------------------------------------------------------
__global__ __launch_bounds__(256, 1)
void precompute_kernel(const float* __restrict__ Zu,
                       const float* __restrict__ Zr,
                       const float* __restrict__ W1,
                       const float* __restrict__ b1,
                       const unsigned long long* __restrict__ eidx,
                       int gu, int Mu, int Mr)
{
    extern __shared__ float smem[];
    float* Ws = smem;                 // [128][128]
    float* As = smem + HDIM * HDIM;   // [128][128]

    if (blockIdx.x == 0 && threadIdx.x == 0) {
        int is64 = 1;
        #pragma unroll
        for (int i = 0; i < 32; ++i)
            if ((eidx[i] >> 32) != 0ull) is64 = 0;
        g_is64 = is64;
    }

    const bool isR = (blockIdx.x >= (unsigned)gu);
    const int  blk = isR ? (blockIdx.x - gu) : blockIdx.x;
    const int  M   = isR ? Mr : Mu;
    const float* __restrict__ Z  = isR ? Zr : Zu;
    const float* __restrict__ Wp = isR ? (W1 + HDIM * HDIM) : W1;
    __half* __restrict__ C       = isR ? g_R : g_U;

    const int tid  = threadIdx.x;
    const int row0 = blk * 128;

    {
        const float4* Wg  = (const float4*)Wp;
        float4*       Ws4 = (float4*)Ws;
        #pragma unroll
        for (int idx = tid; idx < 4096; idx += 256)
            Ws4[idx] = Wg[idx];
    }
    {
        float4* As4 = (float4*)As;
        #pragma unroll
        for (int idx = tid; idx < 4096; idx += 256) {
            int r  = idx >> 5;
            int gr = row0 + r;
            float4 v = make_float4(0.f, 0.f, 0.f, 0.f);
            if (gr < M) v = ((const float4*)Z)[(size_t)gr * 32 + (idx & 31)];
            As4[idx] = v;
        }
    }
    __syncthreads();

    const int tr = tid >> 4, tc = tid & 15;
    const int ra = tr * 4, rb = 64 + tr * 4;
    const int ca = tc * 4, cb = 64 + tc * 4;

    u64 acc2[8][4];
    #pragma unroll
    for (int i = 0; i < 8; ++i)
        #pragma unroll
        for (int j = 0; j < 4; ++j) acc2[i][j] = 0ull;

    #pragma unroll 2
    for (int k = 0; k < HDIM; k += 4) {
        float4 a[8];
        #pragma unroll
        for (int i = 0; i < 4; ++i) {
            a[i]     = *(const float4*)&As[(ra + i) * HDIM + k];
            a[i + 4] = *(const float4*)&As[(rb + i) * HDIM + k];
        }
        #pragma unroll
        for (int kk = 0; kk < 4; ++kk) {
            ulonglong2 w0 = *(const ulonglong2*)&Ws[(k + kk) * HDIM + ca];
            ulonglong2 w1 = *(const ulonglong2*)&Ws[(k + kk) * HDIM + cb];
            u64 wp[4] = {w0.x, w0.y, w1.x, w1.y};
            #pragma unroll
            for (int i = 0; i < 8; ++i) {
                float av = (kk == 0) ? a[i].x : (kk == 1) ? a[i].y :
                           (kk == 2) ? a[i].z : a[i].w;
                u64 ad = pack_dup(av);
                #pragma unroll
                for (int j = 0; j < 4; ++j)
                    ffma2(acc2[i][j], ad, wp[j]);
            }
        }
    }

    float bA[4] = {0.f, 0.f, 0.f, 0.f}, bB[4] = {0.f, 0.f, 0.f, 0.f};
    if (!isR) {
        float4 t = *(const float4*)&b1[ca];
        bA[0] = t.x; bA[1] = t.y; bA[2] = t.z; bA[3] = t.w;
        float4 u = *(const float4*)&b1[cb];
        bB[0] = u.x; bB[1] = u.y; bB[2] = u.z; bB[3] = u.w;
    }

    #pragma unroll
    for (int i = 0; i < 8; ++i) {
        int r  = (i < 4) ? (ra + i) : (rb + i - 4);
        int gr = row0 + r;
        if (gr < M) {
            float2 p0 = unpack2(acc2[i][0]), p1 = unpack2(acc2[i][1]);
            float2 p2 = unpack2(acc2[i][2]), p3 = unpack2(acc2[i][3]);
            __half2 h0 = __float22half2_rn(make_float2(p0.x + bA[0], p0.y + bA[1]));
            __half2 h1 = __float22half2_rn(make_float2(p1.x + bA[2], p1.y + bA[3]));
            __half2 h2 = __float22half2_rn(make_float2(p2.x + bB[0], p2.y + bB[1]));
            __half2 h3 = __float22half2_rn(make_float2(p3.x + bB[2], p3.y + bB[3]));
            uint2 oa, ob;
            oa.x = *(unsigned*)&h0;  oa.y = *(unsigned*)&h1;
            ob.x = *(unsigned*)&h2;  ob.y = *(unsigned*)&h3;
            *(uint2*)&C[(size_t)gr * HDIM + ca] = oa;
            *(uint2*)&C[(size_t)gr * HDIM + cb] = ob;
        }
    }
}

// ---------------------------------------------------------------------------
// Phase 2: four edges per warp (8 lanes each). fp16 row = 256B = 16 uint4
// chunks. Lane l8 loads chunk l8 (line 0 of the row) and chunk l8+8 (line 1):
// each 8-lane LDG.128 group covers exactly one 128B line -> minimal L1
// wavefronts (4 per edge). fp32 dot, 3-step shfl reduce.
// ---------------------------------------------------------------------------
__device__ __forceinline__ float dot8h(uint4 u, uint4 r, float4 w0, float4 w1) {
    const __half2 z2 = __float2half2_rn(0.f);
    __half2 a0 = __hmax2(__hadd2(*(__half2*)&u.x, *(__half2*)&r.x), z2);
    __half2 a1 = __hmax2(__hadd2(*(__half2*)&u.y, *(__half2*)&r.y), z2);
    __half2 a2 = __hmax2(__hadd2(*(__half2*)&u.z, *(__half2*)&r.z), z2);
    __half2 a3 = __hmax2(__hadd2(*(__half2*)&u.w, *(__half2*)&r.w), z2);
    float2 f0 = __half22float2(a0);
    float2 f1 = __half22float2(a1);
    float2 f2 = __half22float2(a2);
    float2 f3 = __half22float2(a3);
    float s;
    s  = f0.x * w0.x;
    s  = fmaf(f0.y, w0.y, s);
    s  = fmaf(f1.x, w0.z, s);
    s  = fmaf(f1.y, w0.w, s);
    s  = fmaf(f2.x, w1.x, s);
    s  = fmaf(f2.y, w1.y, s);
    s  = fmaf(f3.x, w1.z, s);
    s  = fmaf(f3.y, w1.w, s);
    return s;
}

__global__ __launch_bounds__(256)
void edge_kernel(const void* __restrict__ eidx,
                 const float* __restrict__ W2,
                 const float* __restrict__ b2,
                 float* __restrict__ out,
                 int E)
{
    __shared__ float w2s[HDIM];
    const int tid = threadIdx.x;
    if (tid < HDIM) w2s[tid] = W2[tid];
    __syncthreads();

    const int warp = (blockIdx.x * 256 + tid) >> 5;
    const int lane = tid & 31;
    const int sub  = lane >> 3;       // edge slot within warp (0..3)
    const int l8   = lane & 7;        // lane within edge group
    const int e    = warp * 4 + sub;
    if (e >= E) return;               // whole 8-lane group exits together

    int row, col;
    if (g_is64) {
        const long long* p = (const long long*)eidx;
        row = (int)p[e];
        col = (int)p[(size_t)E + e];
    } else {
        const int* p = (const int*)eidx;
        row = p[e];
        col = p[(size_t)E + e];
    }

    // Lane l8 handles chunk l8 (cols 8*l8..8*l8+7) and chunk l8+8
    // (cols 64+8*l8..64+8*l8+7): one full 128B line per 8-lane load group.
    const uint4* Up = (const uint4*)&g_U[(size_t)row * HDIM];
    const uint4* Rp = (const uint4*)&g_R[(size_t)col * HDIM];
    const uint4 ua = Up[l8],     ub = Up[l8 + 8];
    const uint4 ra = Rp[l8],     rb = Rp[l8 + 8];

    const float4* w4 = (const float4*)w2s;
    const float4 w0 = w4[2 * l8],      w1 = w4[2 * l8 + 1];
    const float4 w2 = w4[16 + 2 * l8], w3 = w4[16 + 2 * l8 + 1];

    float s = dot8h(ua, ra, w0, w1) + dot8h(ub, rb, w2, w3);

    const unsigned mask = 0xFFu << (sub * 8);
    #pragma unroll
    for (int off = 4; off; off >>= 1)
        s += __shfl_xor_sync(mask, s, off);

    if (l8 == 0) out[e] = s + __ldg(b2);
}

// ---------------------------------------------------------------------------
extern "C" void kernel_launch(void* const* d_in, const int* in_sizes, int n_in,
                              void* d_out, int out_size)
{
    const float* z_user   = (const float*)d_in[0];
    const float* z_recipe = (const float*)d_in[1];
    const void*  eidx     = d_in[2];
    const float* W1       = (const float*)d_in[3];
    const float* b1       = (const float*)d_in[4];
    const float* W2       = (const float*)d_in[5];
    const float* b2       = (const float*)d_in[6];
    float* out = (float*)d_out;

    const int Mu = in_sizes[0] / HDIM;
    const int Mr = in_sizes[1] / HDIM;
    const int E  = in_sizes[2] / 2;

    const int SMEM = 2 * HDIM * HDIM * (int)sizeof(float);   // 128 KB
    cudaFuncSetAttribute(precompute_kernel,
                         cudaFuncAttributeMaxDynamicSharedMemorySize, SMEM);

    const int gu = (Mu + 127) / 128;
    const int gr = (Mr + 127) / 128;
    precompute_kernel<<<gu + gr, 256, SMEM>>>(z_user, z_recipe, W1, b1,
                                              (const unsigned long long*)eidx,
                                              gu, Mu, Mr);

    edge_kernel<<<(E + 31) / 32, 256>>>(eidx, W2, b2, out, E);
}

// round 5
// speedup vs baseline: 2.1809x; 1.3448x over previous
#include <cuda_runtime.h>
#include <cuda_fp16.h>
#include <mma.h>

using namespace nvcuda;

// ---------------------------------------------------------------------------
// EdgeDecoder: out[e] = relu([zu[row]; zr[col]] @ W1 + b1) @ W2 + b2
// Restructured: U = zu @ W1_top + b1 ; R = zr @ W1_bot
// R5: precompute GEMM on tensor cores via split-fp16 (Markidis):
//     Z = Zh + Zl, W = Wh + Wl ;  C = Ah*Bh + Ah*Bl + Al*Bh (fp32 accum)
//     -> fp32-level accuracy at fp16 HMMA throughput.
// U,R stored fp16; edge kernel: relu(U[row]+R[col]).W2 (fp32 dot).
// ---------------------------------------------------------------------------

#define HDIM 128
#define MAX_USER   100000
#define MAX_RECIPE 50000

__device__ __half g_U[(size_t)MAX_USER * HDIM];    // 25.6 MB
__device__ __half g_R[(size_t)MAX_RECIPE * HDIM];  // 12.8 MB
__device__ int    g_is64;

// smem pitches (halves / floats)
#define APITCH 136              // 128 + 8 pad: conflict-free ldmatrix
#define TILEB  (128 * APITCH * 2)   // 34816 B per half-tile
#define CPITCH 132              // fp32 epilogue staging pitch

// ---------------------------------------------------------------------------
// Phase 1: blocks [0,gu) -> U tiles, [gu,gu+gr) -> R tiles.
// 512 threads, 16 warps. Warp w: rows (w>>1)*16, cols (w&1)*64 of 128x128.
// ---------------------------------------------------------------------------
__global__ __launch_bounds__(512, 1)
void precompute_kernel(const float* __restrict__ Zu,
                       const float* __restrict__ Zr,
                       const float* __restrict__ W1,
                       const float* __restrict__ b1,
                       const unsigned long long* __restrict__ eidx,
                       int gu, int Mu, int Mr)
{
    extern __shared__ __align__(16) char sm[];
    __half* Ah = (__half*)sm;
    __half* Al = (__half*)(sm + TILEB);
    __half* Bh = (__half*)(sm + 2 * TILEB);
    __half* Bl = (__half*)(sm + 3 * TILEB);

    if (blockIdx.x == 0 && threadIdx.x == 0) {
        int is64 = 1;
        #pragma unroll
        for (int i = 0; i < 32; ++i)
            if ((eidx[i] >> 32) != 0ull) is64 = 0;
        g_is64 = is64;
    }

    const bool isR = (blockIdx.x >= (unsigned)gu);
    const int  blk = isR ? (blockIdx.x - gu) : blockIdx.x;
    const int  M   = isR ? Mr : Mu;
    const float* __restrict__ Z  = isR ? Zr : Zu;
    const float* __restrict__ Wp = isR ? (W1 + HDIM * HDIM) : W1;
    __half* __restrict__ C       = isR ? g_R : g_U;

    const int tid  = threadIdx.x;
    const int row0 = blk * 128;

    // Stage B = W tile (128x128), split into hi/lo fp16.
    #pragma unroll
    for (int idx = tid; idx < 4096; idx += 512) {
        const int r  = idx >> 5;
        const int c4 = (idx & 31) * 4;
        float4 v = ((const float4*)Wp)[idx];
        __half hx = __float2half_rn(v.x), hy = __float2half_rn(v.y);
        __half hz = __float2half_rn(v.z), hw = __float2half_rn(v.w);
        __half2 p0 = __halves2half2(hx, hy), p1 = __halves2half2(hz, hw);
        uint2 hh; hh.x = *(unsigned*)&p0; hh.y = *(unsigned*)&p1;
        *(uint2*)&Bh[r * APITCH + c4] = hh;
        __half lx = __float2half_rn(v.x - __half2float(hx));
        __half ly = __float2half_rn(v.y - __half2float(hy));
        __half lz = __float2half_rn(v.z - __half2float(hz));
        __half lw = __float2half_rn(v.w - __half2float(hw));
        __half2 q0 = __halves2half2(lx, ly), q1 = __halves2half2(lz, lw);
        uint2 ll; ll.x = *(unsigned*)&q0; ll.y = *(unsigned*)&q1;
        *(uint2*)&Bl[r * APITCH + c4] = ll;
    }
    // Stage A = Z tile (zero-pad tail rows), split hi/lo.
    #pragma unroll
    for (int idx = tid; idx < 4096; idx += 512) {
        const int r  = idx >> 5;
        const int c4 = (idx & 31) * 4;
        const int gr = row0 + r;
        float4 v = make_float4(0.f, 0.f, 0.f, 0.f);
        if (gr < M) v = ((const float4*)Z)[(size_t)gr * 32 + (idx & 31)];
        __half hx = __float2half_rn(v.x), hy = __float2half_rn(v.y);
        __half hz = __float2half_rn(v.z), hw = __float2half_rn(v.w);
        __half2 p0 = __halves2half2(hx, hy), p1 = __halves2half2(hz, hw);
        uint2 hh; hh.x = *(unsigned*)&p0; hh.y = *(unsigned*)&p1;
        *(uint2*)&Ah[r * APITCH + c4] = hh;
        __half lx = __float2half_rn(v.x - __half2float(hx));
        __half ly = __float2half_rn(v.y - __half2float(hy));
        __half lz = __float2half_rn(v.z - __half2float(hz));
        __half lw = __float2half_rn(v.w - __half2float(hw));
        __half2 q0 = __halves2half2(lx, ly), q1 = __halves2half2(lz, lw);
        uint2 ll; ll.x = *(unsigned*)&q0; ll.y = *(unsigned*)&q1;
        *(uint2*)&Al[r * APITCH + c4] = ll;
    }
    __syncthreads();

    const int warp = tid >> 5;
    const int wm   = warp >> 1;      // 0..7 -> row block of 16
    const int wn   = warp & 1;       // 0..1 -> col block of 64

    wmma::fragment<wmma::accumulator, 16, 16, 16, float> acc[4];
    #pragma unroll
    for (int j = 0; j < 4; ++j) wmma::fill_fragment(acc[j], 0.f);

    wmma::fragment<wmma::matrix_a, 16, 16, 16, __half, wmma::row_major> fAh, fAl;
    wmma::fragment<wmma::matrix_b, 16, 16, 16, __half, wmma::row_major> fBh[4], fBl[4];

    #pragma unroll
    for (int k = 0; k < HDIM; k += 16) {
        wmma::load_matrix_sync(fAh, Ah + (wm * 16) * APITCH + k, APITCH);
        wmma::load_matrix_sync(fAl, Al + (wm * 16) * APITCH + k, APITCH);
        #pragma unroll
        for (int j = 0; j < 4; ++j) {
            wmma::load_matrix_sync(fBh[j], Bh + k * APITCH + wn * 64 + j * 16, APITCH);
            wmma::load_matrix_sync(fBl[j], Bl + k * APITCH + wn * 64 + j * 16, APITCH);
        }
        #pragma unroll
        for (int j = 0; j < 4; ++j) {
            wmma::mma_sync(acc[j], fAh, fBh[j], acc[j]);
            wmma::mma_sync(acc[j], fAh, fBl[j], acc[j]);
            wmma::mma_sync(acc[j], fAl, fBh[j], acc[j]);
        }
    }

    // Epilogue: stage fp32 results in smem, then bias + fp16 convert + store.
    __syncthreads();
    float* Cf = (float*)sm;          // 128 x CPITCH floats = 67.6 KB
    #pragma unroll
    for (int j = 0; j < 4; ++j)
        wmma::store_matrix_sync(Cf + (wm * 16) * CPITCH + wn * 64 + j * 16,
                                acc[j], CPITCH, wmma::mem_row_major);
    __syncthreads();

    #pragma unroll
    for (int idx = tid; idx < 4096; idx += 512) {
        const int r  = idx >> 5;
        const int c4 = (idx & 31) * 4;
        const int gr = row0 + r;
        if (gr < M) {
            float4 v = *(const float4*)&Cf[r * CPITCH + c4];
            if (!isR) {
                const float4 bv = *(const float4*)&b1[c4];
                v.x += bv.x; v.y += bv.y; v.z += bv.z; v.w += bv.w;
            }
            __half2 h0 = __float22half2_rn(make_float2(v.x, v.y));
            __half2 h1 = __float22half2_rn(make_float2(v.z, v.w));
            uint2 o; o.x = *(unsigned*)&h0; o.y = *(unsigned*)&h1;
            *(uint2*)&C[(size_t)gr * HDIM + c4] = o;
        }
    }
}

// ---------------------------------------------------------------------------
// Phase 2: four edges per warp (8 lanes each). Lane l8 loads chunk l8 and
// chunk l8+8: each 8-lane LDG.128 group covers exactly one 128B line.
// fp32 dot, 3-step shfl reduce. (unchanged from R4)
// ---------------------------------------------------------------------------
__device__ __forceinline__ float dot8h(uint4 u, uint4 r, float4 w0, float4 w1) {
    const __half2 z2 = __float2half2_rn(0.f);
    __half2 a0 = __hmax2(__hadd2(*(__half2*)&u.x, *(__half2*)&r.x), z2);
    __half2 a1 = __hmax2(__hadd2(*(__half2*)&u.y, *(__half2*)&r.y), z2);
    __half2 a2 = __hmax2(__hadd2(*(__half2*)&u.z, *(__half2*)&r.z), z2);
    __half2 a3 = __hmax2(__hadd2(*(__half2*)&u.w, *(__half2*)&r.w), z2);
    float2 f0 = __half22float2(a0);
    float2 f1 = __half22float2(a1);
    float2 f2 = __half22float2(a2);
    float2 f3 = __half22float2(a3);
    float s;
    s  = f0.x * w0.x;
    s  = fmaf(f0.y, w0.y, s);
    s  = fmaf(f1.x, w0.z, s);
    s  = fmaf(f1.y, w0.w, s);
    s  = fmaf(f2.x, w1.x, s);
    s  = fmaf(f2.y, w1.y, s);
    s  = fmaf(f3.x, w1.z, s);
    s  = fmaf(f3.y, w1.w, s);
    return s;
}

__global__ __launch_bounds__(256)
void edge_kernel(const void* __restrict__ eidx,
                 const float* __restrict__ W2,
                 const float* __restrict__ b2,
                 float* __restrict__ out,
                 int E)
{
    __shared__ float w2s[HDIM];
    const int tid = threadIdx.x;
    if (tid < HDIM) w2s[tid] = W2[tid];
    __syncthreads();

    const int warp = (blockIdx.x * 256 + tid) >> 5;
    const int lane = tid & 31;
    const int sub  = lane >> 3;
    const int l8   = lane & 7;
    const int e    = warp * 4 + sub;
    if (e >= E) return;

    int row, col;
    if (g_is64) {
        const long long* p = (const long long*)eidx;
        row = (int)p[e];
        col = (int)p[(size_t)E + e];
    } else {
        const int* p = (const int*)eidx;
        row = p[e];
        col = p[(size_t)E + e];
    }

    const uint4* Up = (const uint4*)&g_U[(size_t)row * HDIM];
    const uint4* Rp = (const uint4*)&g_R[(size_t)col * HDIM];
    const uint4 ua = Up[l8],     ub = Up[l8 + 8];
    const uint4 ra = Rp[l8],     rb = Rp[l8 + 8];

    const float4* w4 = (const float4*)w2s;
    const float4 w0 = w4[2 * l8],      w1 = w4[2 * l8 + 1];
    const float4 w2 = w4[16 + 2 * l8], w3 = w4[16 + 2 * l8 + 1];

    float s = dot8h(ua, ra, w0, w1) + dot8h(ub, rb, w2, w3);

    const unsigned mask = 0xFFu << (sub * 8);
    #pragma unroll
    for (int off = 4; off; off >>= 1)
        s += __shfl_xor_sync(mask, s, off);

    if (l8 == 0) out[e] = s + __ldg(b2);
}

// ---------------------------------------------------------------------------
extern "C" void kernel_launch(void* const* d_in, const int* in_sizes, int n_in,
                              void* d_out, int out_size)
{
    const float* z_user   = (const float*)d_in[0];
    const float* z_recipe = (const float*)d_in[1];
    const void*  eidx     = d_in[2];
    const float* W1       = (const float*)d_in[3];
    const float* b1       = (const float*)d_in[4];
    const float* W2       = (const float*)d_in[5];
    const float* b2       = (const float*)d_in[6];
    float* out = (float*)d_out;

    const int Mu = in_sizes[0] / HDIM;
    const int Mr = in_sizes[1] / HDIM;
    const int E  = in_sizes[2] / 2;

    const int SMEM = 4 * TILEB;      // 139264 B
    cudaFuncSetAttribute(precompute_kernel,
                         cudaFuncAttributeMaxDynamicSharedMemorySize, SMEM);

    const int gu = (Mu + 127) / 128;
    const int gr = (Mr + 127) / 128;
    precompute_kernel<<<gu + gr, 512, SMEM>>>(z_user, z_recipe, W1, b1,
                                              (const unsigned long long*)eidx,
                                              gu, Mu, Mr);

    edge_kernel<<<(E + 31) / 32, 256>>>(eidx, W2, b2, out, E);
}

// round 6
// speedup vs baseline: 2.1970x; 1.0074x over previous
#include <cuda_runtime.h>
#include <cuda_fp16.h>
#include <mma.h>

using namespace nvcuda;

// ---------------------------------------------------------------------------
// EdgeDecoder: out[e] = relu([zu[row]; zr[col]] @ W1 + b1) @ W2 + b2
// Restructured: U = zu @ W1_top + b1 ; R = zr @ W1_bot
// Precompute GEMM: tensor cores, split-fp16 (Markidis) -> fp32-level accuracy.
// U,R stored fp16. Edge phase: persistent warps, 4 edges/warp/iter,
// software-pipelined prefetch of next batch to hide L2 latency.
// ---------------------------------------------------------------------------

#define HDIM 128
#define MAX_USER   100000
#define MAX_RECIPE 50000

__device__ __half g_U[(size_t)MAX_USER * HDIM];    // 25.6 MB
__device__ __half g_R[(size_t)MAX_RECIPE * HDIM];  // 12.8 MB
__device__ int    g_is64;

#define APITCH 136
#define TILEB  (128 * APITCH * 2)
#define CPITCH 132

// ---------------------------------------------------------------------------
// Phase 1: split-fp16 tensor-core GEMM (unchanged from R5).
// ---------------------------------------------------------------------------
__global__ __launch_bounds__(512, 1)
void precompute_kernel(const float* __restrict__ Zu,
                       const float* __restrict__ Zr,
                       const float* __restrict__ W1,
                       const float* __restrict__ b1,
                       const unsigned long long* __restrict__ eidx,
                       int gu, int Mu, int Mr)
{
    extern __shared__ __align__(16) char sm[];
    __half* Ah = (__half*)sm;
    __half* Al = (__half*)(sm + TILEB);
    __half* Bh = (__half*)(sm + 2 * TILEB);
    __half* Bl = (__half*)(sm + 3 * TILEB);

    if (blockIdx.x == 0 && threadIdx.x == 0) {
        int is64 = 1;
        #pragma unroll
        for (int i = 0; i < 32; ++i)
            if ((eidx[i] >> 32) != 0ull) is64 = 0;
        g_is64 = is64;
    }

    const bool isR = (blockIdx.x >= (unsigned)gu);
    const int  blk = isR ? (blockIdx.x - gu) : blockIdx.x;
    const int  M   = isR ? Mr : Mu;
    const float* __restrict__ Z  = isR ? Zr : Zu;
    const float* __restrict__ Wp = isR ? (W1 + HDIM * HDIM) : W1;
    __half* __restrict__ C       = isR ? g_R : g_U;

    const int tid  = threadIdx.x;
    const int row0 = blk * 128;

    #pragma unroll
    for (int idx = tid; idx < 4096; idx += 512) {
        const int r  = idx >> 5;
        const int c4 = (idx & 31) * 4;
        float4 v = ((const float4*)Wp)[idx];
        __half hx = __float2half_rn(v.x), hy = __float2half_rn(v.y);
        __half hz = __float2half_rn(v.z), hw = __float2half_rn(v.w);
        __half2 p0 = __halves2half2(hx, hy), p1 = __halves2half2(hz, hw);
        uint2 hh; hh.x = *(unsigned*)&p0; hh.y = *(unsigned*)&p1;
        *(uint2*)&Bh[r * APITCH + c4] = hh;
        __half lx = __float2half_rn(v.x - __half2float(hx));
        __half ly = __float2half_rn(v.y - __half2float(hy));
        __half lz = __float2half_rn(v.z - __half2float(hz));
        __half lw = __float2half_rn(v.w - __half2float(hw));
        __half2 q0 = __halves2half2(lx, ly), q1 = __halves2half2(lz, lw);
        uint2 ll; ll.x = *(unsigned*)&q0; ll.y = *(unsigned*)&q1;
        *(uint2*)&Bl[r * APITCH + c4] = ll;
    }
    #pragma unroll
    for (int idx = tid; idx < 4096; idx += 512) {
        const int r  = idx >> 5;
        const int c4 = (idx & 31) * 4;
        const int gr = row0 + r;
        float4 v = make_float4(0.f, 0.f, 0.f, 0.f);
        if (gr < M) v = ((const float4*)Z)[(size_t)gr * 32 + (idx & 31)];
        __half hx = __float2half_rn(v.x), hy = __float2half_rn(v.y);
        __half hz = __float2half_rn(v.z), hw = __float2half_rn(v.w);
        __half2 p0 = __halves2half2(hx, hy), p1 = __halves2half2(hz, hw);
        uint2 hh; hh.x = *(unsigned*)&p0; hh.y = *(unsigned*)&p1;
        *(uint2*)&Ah[r * APITCH + c4] = hh;
        __half lx = __float2half_rn(v.x - __half2float(hx));
        __half ly = __float2half_rn(v.y - __half2float(hy));
        __half lz = __float2half_rn(v.z - __half2float(hz));
        __half lw = __float2half_rn(v.w - __half2float(hw));
        __half2 q0 = __halves2half2(lx, ly), q1 = __halves2half2(lz, lw);
        uint2 ll; ll.x = *(unsigned*)&q0; ll.y = *(unsigned*)&q1;
        *(uint2*)&Al[r * APITCH + c4] = ll;
    }
    __syncthreads();

    const int warp = tid >> 5;
    const int wm   = warp >> 1;
    const int wn   = warp & 1;

    wmma::fragment<wmma::accumulator, 16, 16, 16, float> acc[4];
    #pragma unroll
    for (int j = 0; j < 4; ++j) wmma::fill_fragment(acc[j], 0.f);

    wmma::fragment<wmma::matrix_a, 16, 16, 16, __half, wmma::row_major> fAh, fAl;
    wmma::fragment<wmma::matrix_b, 16, 16, 16, __half, wmma::row_major> fBh[4], fBl[4];

    #pragma unroll
    for (int k = 0; k < HDIM; k += 16) {
        wmma::load_matrix_sync(fAh, Ah + (wm * 16) * APITCH + k, APITCH);
        wmma::load_matrix_sync(fAl, Al + (wm * 16) * APITCH + k, APITCH);
        #pragma unroll
        for (int j = 0; j < 4; ++j) {
            wmma::load_matrix_sync(fBh[j], Bh + k * APITCH + wn * 64 + j * 16, APITCH);
            wmma::load_matrix_sync(fBl[j], Bl + k * APITCH + wn * 64 + j * 16, APITCH);
        }
        #pragma unroll
        for (int j = 0; j < 4; ++j) {
            wmma::mma_sync(acc[j], fAh, fBh[j], acc[j]);
            wmma::mma_sync(acc[j], fAh, fBl[j], acc[j]);
            wmma::mma_sync(acc[j], fAl, fBh[j], acc[j]);
        }
    }

    __syncthreads();
    float* Cf = (float*)sm;
    #pragma unroll
    for (int j = 0; j < 4; ++j)
        wmma::store_matrix_sync(Cf + (wm * 16) * CPITCH + wn * 64 + j * 16,
                                acc[j], CPITCH, wmma::mem_row_major);
    __syncthreads();

    #pragma unroll
    for (int idx = tid; idx < 4096; idx += 512) {
        const int r  = idx >> 5;
        const int c4 = (idx & 31) * 4;
        const int gr = row0 + r;
        if (gr < M) {
            float4 v = *(const float4*)&Cf[r * CPITCH + c4];
            if (!isR) {
                const float4 bv = *(const float4*)&b1[c4];
                v.x += bv.x; v.y += bv.y; v.z += bv.z; v.w += bv.w;
            }
            __half2 h0 = __float22half2_rn(make_float2(v.x, v.y));
            __half2 h1 = __float22half2_rn(make_float2(v.z, v.w));
            uint2 o; o.x = *(unsigned*)&h0; o.y = *(unsigned*)&h1;
            *(uint2*)&C[(size_t)gr * HDIM + c4] = o;
        }
    }
}

// ---------------------------------------------------------------------------
// Phase 2: persistent warps. 4 edges/warp/iter (8 lanes each); next-iteration
// indices + rows prefetched before computing the current iteration.
// Lane l8 loads chunk l8 and l8+8: each 8-lane group covers one 128B line.
// ---------------------------------------------------------------------------
__device__ __forceinline__ float dot8h(uint4 u, uint4 r, float4 w0, float4 w1) {
    const __half2 z2 = __float2half2_rn(0.f);
    __half2 a0 = __hmax2(__hadd2(*(__half2*)&u.x, *(__half2*)&r.x), z2);
    __half2 a1 = __hmax2(__hadd2(*(__half2*)&u.y, *(__half2*)&r.y), z2);
    __half2 a2 = __hmax2(__hadd2(*(__half2*)&u.z, *(__half2*)&r.z), z2);
    __half2 a3 = __hmax2(__hadd2(*(__half2*)&u.w, *(__half2*)&r.w), z2);
    float2 f0 = __half22float2(a0);
    float2 f1 = __half22float2(a1);
    float2 f2 = __half22float2(a2);
    float2 f3 = __half22float2(a3);
    float s;
    s  = f0.x * w0.x;
    s  = fmaf(f0.y, w0.y, s);
    s  = fmaf(f1.x, w0.z, s);
    s  = fmaf(f1.y, w0.w, s);
    s  = fmaf(f2.x, w1.x, s);
    s  = fmaf(f2.y, w1.y, s);
    s  = fmaf(f3.x, w1.z, s);
    s  = fmaf(f3.y, w1.w, s);
    return s;
}

__device__ __forceinline__ void load_edge(const void* eidx, int is64, int e,
                                          int E, int l8,
                                          uint4& ua, uint4& ub,
                                          uint4& ra, uint4& rb)
{
    int row, col;
    if (is64) {
        const long long* p = (const long long*)eidx;
        row = (int)p[e];
        col = (int)p[(size_t)E + e];
    } else {
        const int* p = (const int*)eidx;
        row = p[e];
        col = p[(size_t)E + e];
    }
    const uint4* Up = (const uint4*)&g_U[(size_t)row * HDIM];
    const uint4* Rp = (const uint4*)&g_R[(size_t)col * HDIM];
    ua = Up[l8];  ub = Up[l8 + 8];
    ra = Rp[l8];  rb = Rp[l8 + 8];
}

__global__ __launch_bounds__(256, 3)
void edge_kernel(const void* __restrict__ eidx,
                 const float* __restrict__ W2,
                 const float* __restrict__ b2,
                 float* __restrict__ out,
                 int E, int TW)
{
    __shared__ float w2s[HDIM];
    const int tid = threadIdx.x;
    if (tid < HDIM) w2s[tid] = W2[tid];
    __syncthreads();

    const int lane = tid & 31;
    const int sub  = lane >> 3;
    const int l8   = lane & 7;
    const int wg   = (blockIdx.x * 256 + tid) >> 5;   // global warp id
    const int step = TW * 4;
    const int is64 = g_is64;
    const float b2v = __ldg(b2);

    const float4* w4 = (const float4*)w2s;
    const float4 wv0 = w4[2 * l8],      wv1 = w4[2 * l8 + 1];
    const float4 wv2 = w4[16 + 2 * l8], wv3 = w4[16 + 2 * l8 + 1];

    int base = wg * 4;
    if (base >= E) return;

    int  e = base + sub;
    bool valid = (e < E);
    uint4 ua, ub, ra, rb;
    if (valid) load_edge(eidx, is64, e, E, l8, ua, ub, ra, rb);

    const unsigned mask = 0xFFu << (sub * 8);

    while (base < E) {
        const int nbase = base + step;
        const int en    = nbase + sub;
        const bool vnext = (nbase < E) && (en < E);

        // Prefetch next batch (independent of current compute).
        uint4 ua_n, ub_n, ra_n, rb_n;
        if (vnext) load_edge(eidx, is64, en, E, l8, ua_n, ub_n, ra_n, rb_n);

        if (valid) {
            float s = dot8h(ua, ra, wv0, wv1) + dot8h(ub, rb, wv2, wv3);
            #pragma unroll
            for (int off = 4; off; off >>= 1)
                s += __shfl_xor_sync(mask, s, off);
            if (l8 == 0) out[e] = s + b2v;
        }

        base = nbase;
        e = en;
        valid = vnext;
        ua = ua_n; ub = ub_n; ra = ra_n; rb = rb_n;
    }
}

// ---------------------------------------------------------------------------
extern "C" void kernel_launch(void* const* d_in, const int* in_sizes, int n_in,
                              void* d_out, int out_size)
{
    const float* z_user   = (const float*)d_in[0];
    const float* z_recipe = (const float*)d_in[1];
    const void*  eidx     = d_in[2];
    const float* W1       = (const float*)d_in[3];
    const float* b1       = (const float*)d_in[4];
    const float* W2       = (const float*)d_in[5];
    const float* b2       = (const float*)d_in[6];
    float* out = (float*)d_out;

    const int Mu = in_sizes[0] / HDIM;
    const int Mr = in_sizes[1] / HDIM;
    const int E  = in_sizes[2] / 2;

    const int SMEM = 4 * TILEB;
    cudaFuncSetAttribute(precompute_kernel,
                         cudaFuncAttributeMaxDynamicSharedMemorySize, SMEM);

    const int gu = (Mu + 127) / 128;
    const int gr = (Mr + 127) / 128;
    precompute_kernel<<<gu + gr, 512, SMEM>>>(z_user, z_recipe, W1, b1,
                                              (const unsigned long long*)eidx,
                                              gu, Mu, Mr);

    const int NB = 148 * 3;          // persistent grid (3 blocks/SM at 256thr)
    const int TW = NB * 8;           // total warps
    edge_kernel<<<NB, 256>>>(eidx, W2, b2, out, E, TW);
}

// round 7
// speedup vs baseline: 2.6784x; 1.2191x over previous
#include <cuda_runtime.h>
#include <cuda_fp16.h>
#include <mma.h>

using namespace nvcuda;

// ---------------------------------------------------------------------------
// EdgeDecoder: out[e] = relu([zu[row]; zr[col]] @ W1 + b1) @ W2 + b2
// Restructured: U = zu @ W1_top + b1 ; R = zr @ W1_bot
// R7: plain fp16 HMMA precompute (single product, fp32 accum). U/R are stored
//     fp16 anyway (that storage dominates rel_err at 3.6e-4); fp16 input
//     rounding adds ~2.8e-4 incoherent -> total ~4.6e-4, 2.2x under 1e-3.
//     2 CTAs/SM for stage/MMA overlap.
// Edge phase: persistent warps at the L2 random-line ceiling (unchanged).
// ---------------------------------------------------------------------------

#define HDIM 128
#define MAX_USER   100000
#define MAX_RECIPE 50000

__device__ __half g_U[(size_t)MAX_USER * HDIM];    // 25.6 MB
__device__ __half g_R[(size_t)MAX_RECIPE * HDIM];  // 12.8 MB
__device__ int    g_is64;

#define APITCH 136                    // 128 + 8 pad: conflict-free ldmatrix
#define TILEB  (128 * APITCH * 2)     // 34816 B per fp16 tile
#define CPITCH 132                    // fp32 epilogue staging pitch

// ---------------------------------------------------------------------------
// Phase 1: blocks [0,gu) -> U tiles, [gu,gu+gr) -> R tiles.
// 512 threads, 16 warps; warp w: rows (w>>1)*16, cols (w&1)*64.
// A = Z tile fp16, B = W tile fp16 ([k][n] row-major), fp32 accumulators.
// ---------------------------------------------------------------------------
__global__ __launch_bounds__(512, 2)
void precompute_kernel(const float* __restrict__ Zu,
                       const float* __restrict__ Zr,
                       const float* __restrict__ W1,
                       const float* __restrict__ b1,
                       const unsigned long long* __restrict__ eidx,
                       int gu, int Mu, int Mr)
{
    extern __shared__ __align__(16) char sm[];
    __half* Ah = (__half*)sm;                // [128][APITCH]
    __half* Bh = (__half*)(sm + TILEB);      // [128][APITCH]

    if (blockIdx.x == 0 && threadIdx.x == 0) {
        int is64 = 1;
        #pragma unroll
        for (int i = 0; i < 32; ++i)
            if ((eidx[i] >> 32) != 0ull) is64 = 0;
        g_is64 = is64;
    }

    const bool isR = (blockIdx.x >= (unsigned)gu);
    const int  blk = isR ? (blockIdx.x - gu) : blockIdx.x;
    const int  M   = isR ? Mr : Mu;
    const float* __restrict__ Z  = isR ? Zr : Zu;
    const float* __restrict__ Wp = isR ? (W1 + HDIM * HDIM) : W1;
    __half* __restrict__ C       = isR ? g_R : g_U;

    const int tid  = threadIdx.x;
    const int row0 = blk * 128;

    // Stage B = W tile (128x128 fp16).
    #pragma unroll
    for (int idx = tid; idx < 4096; idx += 512) {
        const int r  = idx >> 5;
        const int c4 = (idx & 31) * 4;
        float4 v = ((const float4*)Wp)[idx];
        __half2 p0 = __float22half2_rn(make_float2(v.x, v.y));
        __half2 p1 = __float22half2_rn(make_float2(v.z, v.w));
        uint2 hh; hh.x = *(unsigned*)&p0; hh.y = *(unsigned*)&p1;
        *(uint2*)&Bh[r * APITCH + c4] = hh;
    }
    // Stage A = Z tile (zero-pad tail rows).
    #pragma unroll
    for (int idx = tid; idx < 4096; idx += 512) {
        const int r  = idx >> 5;
        const int c4 = (idx & 31) * 4;
        const int gr = row0 + r;
        float4 v = make_float4(0.f, 0.f, 0.f, 0.f);
        if (gr < M) v = ((const float4*)Z)[(size_t)gr * 32 + (idx & 31)];
        __half2 p0 = __float22half2_rn(make_float2(v.x, v.y));
        __half2 p1 = __float22half2_rn(make_float2(v.z, v.w));
        uint2 hh; hh.x = *(unsigned*)&p0; hh.y = *(unsigned*)&p1;
        *(uint2*)&Ah[r * APITCH + c4] = hh;
    }
    __syncthreads();

    const int warp = tid >> 5;
    const int wm   = warp >> 1;      // 0..7 -> 16-row block
    const int wn   = warp & 1;       // 0..1 -> 64-col block

    wmma::fragment<wmma::accumulator, 16, 16, 16, float> acc[4];
    #pragma unroll
    for (int j = 0; j < 4; ++j) wmma::fill_fragment(acc[j], 0.f);

    wmma::fragment<wmma::matrix_a, 16, 16, 16, __half, wmma::row_major> fA;
    wmma::fragment<wmma::matrix_b, 16, 16, 16, __half, wmma::row_major> fB;

    #pragma unroll
    for (int k = 0; k < HDIM; k += 16) {
        wmma::load_matrix_sync(fA, Ah + (wm * 16) * APITCH + k, APITCH);
        #pragma unroll
        for (int j = 0; j < 4; ++j) {
            wmma::load_matrix_sync(fB, Bh + k * APITCH + wn * 64 + j * 16, APITCH);
            wmma::mma_sync(acc[j], fA, fB, acc[j]);
        }
    }

    // Epilogue: stage fp32 in smem (reuse tiles), bias + fp16 convert + store.
    __syncthreads();
    float* Cf = (float*)sm;          // 128 x CPITCH floats = 67.6 KB <= 68 KB
    #pragma unroll
    for (int j = 0; j < 4; ++j)
        wmma::store_matrix_sync(Cf + (wm * 16) * CPITCH + wn * 64 + j * 16,
                                acc[j], CPITCH, wmma::mem_row_major);
    __syncthreads();

    #pragma unroll
    for (int idx = tid; idx < 4096; idx += 512) {
        const int r  = idx >> 5;
        const int c4 = (idx & 31) * 4;
        const int gr = row0 + r;
        if (gr < M) {
            float4 v = *(const float4*)&Cf[r * CPITCH + c4];
            if (!isR) {
                const float4 bv = *(const float4*)&b1[c4];
                v.x += bv.x; v.y += bv.y; v.z += bv.z; v.w += bv.w;
            }
            __half2 h0 = __float22half2_rn(make_float2(v.x, v.y));
            __half2 h1 = __float22half2_rn(make_float2(v.z, v.w));
            uint2 o; o.x = *(unsigned*)&h0; o.y = *(unsigned*)&h1;
            *(uint2*)&C[(size_t)gr * HDIM + c4] = o;
        }
    }
}

// ---------------------------------------------------------------------------
// Phase 2: persistent warps, 4 edges/warp/iter (8 lanes each), next-batch
// prefetch. At the L2 random-line ceiling (~3.9 KB/cyc chip).
// ---------------------------------------------------------------------------
__device__ __forceinline__ float dot8h(uint4 u, uint4 r, float4 w0, float4 w1) {
    const __half2 z2 = __float2half2_rn(0.f);
    __half2 a0 = __hmax2(__hadd2(*(__half2*)&u.x, *(__half2*)&r.x), z2);
    __half2 a1 = __hmax2(__hadd2(*(__half2*)&u.y, *(__half2*)&r.y), z2);
    __half2 a2 = __hmax2(__hadd2(*(__half2*)&u.z, *(__half2*)&r.z), z2);
    __half2 a3 = __hmax2(__hadd2(*(__half2*)&u.w, *(__half2*)&r.w), z2);
    float2 f0 = __half22float2(a0);
    float2 f1 = __half22float2(a1);
    float2 f2 = __half22float2(a2);
    float2 f3 = __half22float2(a3);
    float s;
    s  = f0.x * w0.x;
    s  = fmaf(f0.y, w0.y, s);
    s  = fmaf(f1.x, w0.z, s);
    s  = fmaf(f1.y, w0.w, s);
    s  = fmaf(f2.x, w1.x, s);
    s  = fmaf(f2.y, w1.y, s);
    s  = fmaf(f3.x, w1.z, s);
    s  = fmaf(f3.y, w1.w, s);
    return s;
}

__device__ __forceinline__ void load_edge(const void* eidx, int is64, int e,
                                          int E, int l8,
                                          uint4& ua, uint4& ub,
                                          uint4& ra, uint4& rb)
{
    int row, col;
    if (is64) {
        const long long* p = (const long long*)eidx;
        row = (int)p[e];
        col = (int)p[(size_t)E + e];
    } else {
        const int* p = (const int*)eidx;
        row = p[e];
        col = p[(size_t)E + e];
    }
    const uint4* Up = (const uint4*)&g_U[(size_t)row * HDIM];
    const uint4* Rp = (const uint4*)&g_R[(size_t)col * HDIM];
    ua = Up[l8];  ub = Up[l8 + 8];
    ra = Rp[l8];  rb = Rp[l8 + 8];
}

__global__ __launch_bounds__(256, 3)
void edge_kernel(const void* __restrict__ eidx,
                 const float* __restrict__ W2,
                 const float* __restrict__ b2,
                 float* __restrict__ out,
                 int E, int TW)
{
    __shared__ float w2s[HDIM];
    const int tid = threadIdx.x;
    if (tid < HDIM) w2s[tid] = W2[tid];
    __syncthreads();

    const int lane = tid & 31;
    const int sub  = lane >> 3;
    const int l8   = lane & 7;
    const int wg   = (blockIdx.x * 256 + tid) >> 5;
    const int step = TW * 4;
    const int is64 = g_is64;
    const float b2v = __ldg(b2);

    const float4* w4 = (const float4*)w2s;
    const float4 wv0 = w4[2 * l8],      wv1 = w4[2 * l8 + 1];
    const float4 wv2 = w4[16 + 2 * l8], wv3 = w4[16 + 2 * l8 + 1];

    int base = wg * 4;
    if (base >= E) return;

    int  e = base + sub;
    bool valid = (e < E);
    uint4 ua, ub, ra, rb;
    if (valid) load_edge(eidx, is64, e, E, l8, ua, ub, ra, rb);

    const unsigned mask = 0xFFu << (sub * 8);

    while (base < E) {
        const int nbase = base + step;
        const int en    = nbase + sub;
        const bool vnext = (nbase < E) && (en < E);

        uint4 ua_n, ub_n, ra_n, rb_n;
        if (vnext) load_edge(eidx, is64, en, E, l8, ua_n, ub_n, ra_n, rb_n);

        if (valid) {
            float s = dot8h(ua, ra, wv0, wv1) + dot8h(ub, rb, wv2, wv3);
            #pragma unroll
            for (int off = 4; off; off >>= 1)
                s += __shfl_xor_sync(mask, s, off);
            if (l8 == 0) out[e] = s + b2v;
        }

        base = nbase;
        e = en;
        valid = vnext;
        ua = ua_n; ub = ub_n; ra = ra_n; rb = rb_n;
    }
}

// ---------------------------------------------------------------------------
extern "C" void kernel_launch(void* const* d_in, const int* in_sizes, int n_in,
                              void* d_out, int out_size)
{
    const float* z_user   = (const float*)d_in[0];
    const float* z_recipe = (const float*)d_in[1];
    const void*  eidx     = d_in[2];
    const float* W1       = (const float*)d_in[3];
    const float* b1       = (const float*)d_in[4];
    const float* W2       = (const float*)d_in[5];
    const float* b2       = (const float*)d_in[6];
    float* out = (float*)d_out;

    const int Mu = in_sizes[0] / HDIM;
    const int Mr = in_sizes[1] / HDIM;
    const int E  = in_sizes[2] / 2;

    const int SMEM = 2 * TILEB;      // 69632 B -> 2 CTAs/SM
    cudaFuncSetAttribute(precompute_kernel,
                         cudaFuncAttributeMaxDynamicSharedMemorySize, SMEM);

    const int gu = (Mu + 127) / 128;
    const int gr = (Mr + 127) / 128;
    precompute_kernel<<<gu + gr, 512, SMEM>>>(z_user, z_recipe, W1, b1,
                                              (const unsigned long long*)eidx,
                                              gu, Mu, Mr);

    const int NB = 148 * 3;
    const int TW = NB * 8;
    edge_kernel<<<NB, 256>>>(eidx, W2, b2, out, E, TW);
}

// round 8
// speedup vs baseline: 2.7168x; 1.0143x over previous
#include <cuda_runtime.h>
#include <cuda_fp16.h>
#include <mma.h>

using namespace nvcuda;

// ---------------------------------------------------------------------------
// EdgeDecoder: out[e] = relu([zu[row]; zr[col]] @ W1 + b1) @ W2 + b2
// Restructured: U = zu @ W1_top + b1 ; R = zr @ W1_bot  (fp16 HMMA, fp32 acc)
// U,R stored fp16. R8: counting-sort edges by row -> U gathers become L1
// hits (~20 edges/row); only R rows remain random at the L2 line ceiling.
// ---------------------------------------------------------------------------

#define HDIM 128
#define MAX_USER   100000
#define MAX_RECIPE 50000
#define MAX_E      (1 << 20)          // 1,048,576 >= 1e6
#define NBINS      50176              // 1024 * 49 bins (covers row < 50176)
#define SCAN_CHUNK 49

__device__ __half g_U[(size_t)MAX_USER * HDIM];    // 25.6 MB
__device__ __half g_R[(size_t)MAX_RECIPE * HDIM];  // 12.8 MB
__device__ int    g_is64;
__device__ int    g_hist[NBINS];
__device__ int    g_offs[NBINS];
__device__ unsigned long long g_sorted[MAX_E];     // row:22 | col:22 | eid:20

#define APITCH 136
#define TILEB  (128 * APITCH * 2)
#define CPITCH 132

// ---------------------------------------------------------------------------
// Phase 1: fp16 HMMA precompute (unchanged from R7). Also sets g_is64.
// ---------------------------------------------------------------------------
__global__ __launch_bounds__(512, 2)
void precompute_kernel(const float* __restrict__ Zu,
                       const float* __restrict__ Zr,
                       const float* __restrict__ W1,
                       const float* __restrict__ b1,
                       const unsigned long long* __restrict__ eidx,
                       int gu, int Mu, int Mr)
{
    extern __shared__ __align__(16) char sm[];
    __half* Ah = (__half*)sm;
    __half* Bh = (__half*)(sm + TILEB);

    if (blockIdx.x == 0 && threadIdx.x == 0) {
        int is64 = 1;
        #pragma unroll
        for (int i = 0; i < 32; ++i)
            if ((eidx[i] >> 32) != 0ull) is64 = 0;
        g_is64 = is64;
    }

    const bool isR = (blockIdx.x >= (unsigned)gu);
    const int  blk = isR ? (blockIdx.x - gu) : blockIdx.x;
    const int  M   = isR ? Mr : Mu;
    const float* __restrict__ Z  = isR ? Zr : Zu;
    const float* __restrict__ Wp = isR ? (W1 + HDIM * HDIM) : W1;
    __half* __restrict__ C       = isR ? g_R : g_U;

    const int tid  = threadIdx.x;
    const int row0 = blk * 128;

    #pragma unroll
    for (int idx = tid; idx < 4096; idx += 512) {
        const int r  = idx >> 5;
        const int c4 = (idx & 31) * 4;
        float4 v = ((const float4*)Wp)[idx];
        __half2 p0 = __float22half2_rn(make_float2(v.x, v.y));
        __half2 p1 = __float22half2_rn(make_float2(v.z, v.w));
        uint2 hh; hh.x = *(unsigned*)&p0; hh.y = *(unsigned*)&p1;
        *(uint2*)&Bh[r * APITCH + c4] = hh;
    }
    #pragma unroll
    for (int idx = tid; idx < 4096; idx += 512) {
        const int r  = idx >> 5;
        const int c4 = (idx & 31) * 4;
        const int gr = row0 + r;
        float4 v = make_float4(0.f, 0.f, 0.f, 0.f);
        if (gr < M) v = ((const float4*)Z)[(size_t)gr * 32 + (idx & 31)];
        __half2 p0 = __float22half2_rn(make_float2(v.x, v.y));
        __half2 p1 = __float22half2_rn(make_float2(v.z, v.w));
        uint2 hh; hh.x = *(unsigned*)&p0; hh.y = *(unsigned*)&p1;
        *(uint2*)&Ah[r * APITCH + c4] = hh;
    }
    __syncthreads();

    const int warp = tid >> 5;
    const int wm   = warp >> 1;
    const int wn   = warp & 1;

    wmma::fragment<wmma::accumulator, 16, 16, 16, float> acc[4];
    #pragma unroll
    for (int j = 0; j < 4; ++j) wmma::fill_fragment(acc[j], 0.f);

    wmma::fragment<wmma::matrix_a, 16, 16, 16, __half, wmma::row_major> fA;
    wmma::fragment<wmma::matrix_b, 16, 16, 16, __half, wmma::row_major> fB;

    #pragma unroll
    for (int k = 0; k < HDIM; k += 16) {
        wmma::load_matrix_sync(fA, Ah + (wm * 16) * APITCH + k, APITCH);
        #pragma unroll
        for (int j = 0; j < 4; ++j) {
            wmma::load_matrix_sync(fB, Bh + k * APITCH + wn * 64 + j * 16, APITCH);
            wmma::mma_sync(acc[j], fA, fB, acc[j]);
        }
    }

    __syncthreads();
    float* Cf = (float*)sm;
    #pragma unroll
    for (int j = 0; j < 4; ++j)
        wmma::store_matrix_sync(Cf + (wm * 16) * CPITCH + wn * 64 + j * 16,
                                acc[j], CPITCH, wmma::mem_row_major);
    __syncthreads();

    #pragma unroll
    for (int idx = tid; idx < 4096; idx += 512) {
        const int r  = idx >> 5;
        const int c4 = (idx & 31) * 4;
        const int gr = row0 + r;
        if (gr < M) {
            float4 v = *(const float4*)&Cf[r * CPITCH + c4];
            if (!isR) {
                const float4 bv = *(const float4*)&b1[c4];
                v.x += bv.x; v.y += bv.y; v.z += bv.z; v.w += bv.w;
            }
            __half2 h0 = __float22half2_rn(make_float2(v.x, v.y));
            __half2 h1 = __float22half2_rn(make_float2(v.z, v.w));
            uint2 o; o.x = *(unsigned*)&h0; o.y = *(unsigned*)&h1;
            *(uint2*)&C[(size_t)gr * HDIM + c4] = o;
        }
    }
}

// ---------------------------------------------------------------------------
// Counting sort of edges by row.
// ---------------------------------------------------------------------------
__device__ __forceinline__ void load_idx(const void* eidx, int is64, int e,
                                         int E, int& row, int& col)
{
    if (is64) {
        const long long* p = (const long long*)eidx;
        row = (int)p[e];
        col = (int)p[(size_t)E + e];
    } else {
        const int* p = (const int*)eidx;
        row = p[e];
        col = p[(size_t)E + e];
    }
}

__global__ void zero_hist_kernel() {
    int i = blockIdx.x * blockDim.x + threadIdx.x;
    if (i < NBINS) g_hist[i] = 0;
}

__global__ void hist_kernel(const void* __restrict__ eidx, int E) {
    const int is64 = g_is64;
    for (int e = blockIdx.x * blockDim.x + threadIdx.x; e < E;
         e += gridDim.x * blockDim.x) {
        int row, col;
        load_idx(eidx, is64, e, E, row, col);
        atomicAdd(&g_hist[row], 1);
    }
}

__global__ __launch_bounds__(1024, 1)
void scan_kernel() {
    __shared__ int part[1024];
    const int t    = threadIdx.x;
    const int base = t * SCAN_CHUNK;

    int s = 0;
    #pragma unroll
    for (int i = 0; i < SCAN_CHUNK; ++i) s += g_hist[base + i];
    part[t] = s;
    __syncthreads();

    // Hillis-Steele inclusive scan over 1024 partials.
    for (int off = 1; off < 1024; off <<= 1) {
        int v = (t >= off) ? part[t - off] : 0;
        __syncthreads();
        part[t] += v;
        __syncthreads();
    }

    int run = part[t] - s;   // exclusive prefix of this thread's chunk
    #pragma unroll
    for (int i = 0; i < SCAN_CHUNK; ++i) {
        int h = g_hist[base + i];
        g_offs[base + i] = run;
        run += h;
    }
}

__global__ void scatter_kernel(const void* __restrict__ eidx, int E) {
    const int is64 = g_is64;
    for (int e = blockIdx.x * blockDim.x + threadIdx.x; e < E;
         e += gridDim.x * blockDim.x) {
        int row, col;
        load_idx(eidx, is64, e, E, row, col);
        int pos = atomicAdd(&g_offs[row], 1);
        g_sorted[pos] = ((unsigned long long)row << 42)
                      | ((unsigned long long)col << 20)
                      | (unsigned)e;
    }
}

// ---------------------------------------------------------------------------
// Phase 2 (sorted): 4 edges/warp (8 lanes each) over the row-sorted list.
// Consecutive edges share U rows (~20/row) -> U gathers are L1 hits; R rows
// random (L2). Result scattered to out[eid].
// ---------------------------------------------------------------------------
__device__ __forceinline__ float dot8h(uint4 u, uint4 r, float4 w0, float4 w1) {
    const __half2 z2 = __float2half2_rn(0.f);
    __half2 a0 = __hmax2(__hadd2(*(__half2*)&u.x, *(__half2*)&r.x), z2);
    __half2 a1 = __hmax2(__hadd2(*(__half2*)&u.y, *(__half2*)&r.y), z2);
    __half2 a2 = __hmax2(__hadd2(*(__half2*)&u.z, *(__half2*)&r.z), z2);
    __half2 a3 = __hmax2(__hadd2(*(__half2*)&u.w, *(__half2*)&r.w), z2);
    float2 f0 = __half22float2(a0);
    float2 f1 = __half22float2(a1);
    float2 f2 = __half22float2(a2);
    float2 f3 = __half22float2(a3);
    float s;
    s  = f0.x * w0.x;
    s  = fmaf(f0.y, w0.y, s);
    s  = fmaf(f1.x, w0.z, s);
    s  = fmaf(f1.y, w0.w, s);
    s  = fmaf(f2.x, w1.x, s);
    s  = fmaf(f2.y, w1.y, s);
    s  = fmaf(f3.x, w1.z, s);
    s  = fmaf(f3.y, w1.w, s);
    return s;
}

__global__ __launch_bounds__(256)
void edge_sorted_kernel(const float* __restrict__ W2,
                        const float* __restrict__ b2,
                        float* __restrict__ out,
                        int E)
{
    __shared__ float w2s[HDIM];
    const int tid = threadIdx.x;
    if (tid < HDIM) w2s[tid] = W2[tid];
    __syncthreads();

    const int warp = (blockIdx.x * 256 + tid) >> 5;
    const int lane = tid & 31;
    const int sub  = lane >> 3;
    const int l8   = lane & 7;
    const int i    = warp * 4 + sub;      // sorted position
    if (i >= E) return;

    const unsigned long long pk = g_sorted[i];
    const int row = (int)(pk >> 42);
    const int col = (int)((pk >> 20) & 0x3FFFFF);
    const int eid = (int)(pk & 0xFFFFF);

    const uint4* Up = (const uint4*)&g_U[(size_t)row * HDIM];
    const uint4* Rp = (const uint4*)&g_R[(size_t)col * HDIM];
    const uint4 ua = Up[l8],  ub = Up[l8 + 8];
    const uint4 ra = Rp[l8],  rb = Rp[l8 + 8];

    const float4* w4 = (const float4*)w2s;
    const float4 w0 = w4[2 * l8],      w1 = w4[2 * l8 + 1];
    const float4 w2 = w4[16 + 2 * l8], w3 = w4[16 + 2 * l8 + 1];

    float s = dot8h(ua, ra, w0, w1) + dot8h(ub, rb, w2, w3);

    const unsigned mask = 0xFFu << (sub * 8);
    #pragma unroll
    for (int off = 4; off; off >>= 1)
        s += __shfl_xor_sync(mask, s, off);

    if (l8 == 0) out[eid] = s + __ldg(b2);
}

// Fallback (unsorted) for out-of-range shapes.
__global__ __launch_bounds__(256)
void edge_kernel(const void* __restrict__ eidx,
                 const float* __restrict__ W2,
                 const float* __restrict__ b2,
                 float* __restrict__ out,
                 int E)
{
    __shared__ float w2s[HDIM];
    const int tid = threadIdx.x;
    if (tid < HDIM) w2s[tid] = W2[tid];
    __syncthreads();

    const int warp = (blockIdx.x * 256 + tid) >> 5;
    const int lane = tid & 31;
    const int sub  = lane >> 3;
    const int l8   = lane & 7;
    const int e    = warp * 4 + sub;
    if (e >= E) return;

    int row, col;
    load_idx(eidx, g_is64, e, E, row, col);

    const uint4* Up = (const uint4*)&g_U[(size_t)row * HDIM];
    const uint4* Rp = (const uint4*)&g_R[(size_t)col * HDIM];
    const uint4 ua = Up[l8],  ub = Up[l8 + 8];
    const uint4 ra = Rp[l8],  rb = Rp[l8 + 8];

    const float4* w4 = (const float4*)w2s;
    const float4 w0 = w4[2 * l8],      w1 = w4[2 * l8 + 1];
    const float4 w2 = w4[16 + 2 * l8], w3 = w4[16 + 2 * l8 + 1];

    float s = dot8h(ua, ra, w0, w1) + dot8h(ub, rb, w2, w3);

    const unsigned mask = 0xFFu << (sub * 8);
    #pragma unroll
    for (int off = 4; off; off >>= 1)
        s += __shfl_xor_sync(mask, s, off);

    if (l8 == 0) out[e] = s + __ldg(b2);
}

// ---------------------------------------------------------------------------
extern "C" void kernel_launch(void* const* d_in, const int* in_sizes, int n_in,
                              void* d_out, int out_size)
{
    const float* z_user   = (const float*)d_in[0];
    const float* z_recipe = (const float*)d_in[1];
    const void*  eidx     = d_in[2];
    const float* W1       = (const float*)d_in[3];
    const float* b1       = (const float*)d_in[4];
    const float* W2       = (const float*)d_in[5];
    const float* b2       = (const float*)d_in[6];
    float* out = (float*)d_out;

    const int Mu = in_sizes[0] / HDIM;
    const int Mr = in_sizes[1] / HDIM;
    const int E  = in_sizes[2] / 2;

    const int SMEM = 2 * TILEB;
    cudaFuncSetAttribute(precompute_kernel,
                         cudaFuncAttributeMaxDynamicSharedMemorySize, SMEM);

    const int gu = (Mu + 127) / 128;
    const int gr = (Mr + 127) / 128;
    precompute_kernel<<<gu + gr, 512, SMEM>>>(z_user, z_recipe, W1, b1,
                                              (const unsigned long long*)eidx,
                                              gu, Mu, Mr);

    // Sorted path valid when rows/cols fit 22 bits, eid fits 20 bits, and
    // rows fall inside the histogram range.
    const bool sortable = (E <= MAX_E) && (Mu <= NBINS) && (Mr < (1 << 22));
    if (sortable) {
        zero_hist_kernel<<<(NBINS + 255) / 256, 256>>>();
        hist_kernel<<<1024, 256>>>(eidx, E);
        scan_kernel<<<1, 1024>>>();
        scatter_kernel<<<1024, 256>>>(eidx, E);
        edge_sorted_kernel<<<(E + 31) / 32, 256>>>(W2, b2, out, E);
    } else {
        edge_kernel<<<(E + 31) / 32, 256>>>(eidx, W2, b2, out, E);
    }
}